// round 2
// baseline (speedup 1.0000x reference)
#include <cuda_runtime.h>
#include <cuda_bf16.h>
#include <math.h>

// Problem constants
#define BATCH 2
#define SEQ 2048
#define DMODEL 2048
#define NHEADS 16
#define DH 128
#define PAST 2048
#define TOTAL 4096          // PAST + SEQ
#define MROWS (BATCH*SEQ)   // 4096

// Output layout: out (B,S,D) | K (B*H, TOTAL, DH) | V (B*H, TOTAL, DH)
#define OUT_ELEMS   ((size_t)BATCH*SEQ*DMODEL)            // 8,388,608
#define KV_ELEMS    ((size_t)BATCH*NHEADS*TOTAL*DH)       // 16,777,216

// Scratch (device globals — no allocations allowed)
__device__ float g_Q[(size_t)BATCH*NHEADS*SEQ*DH];    // (bh, s, dh)
__device__ float g_attn[(size_t)MROWS*DMODEL];        // (b*s, d_model) pre-Wo

// ---------------------------------------------------------------------------
// GEMM: C[m,n] = sum_k A[m,k] * B[n,k]   (A: MxK row-major, B: NxK row-major)
// mode 0: dst[m*N + n] = acc                     (plain row-major)
// mode 1: head-split scatter:
//   b = m/SEQ, s = m%SEQ, h = n/DH, d = n%DH
//   dst[(b*NHEADS + h)*total_len*DH + (row_off + s)*DH + d] = acc
// ---------------------------------------------------------------------------
#define BM 128
#define BN 128
#define BK 16

__global__ __launch_bounds__(256)
void gemm_nt_kernel(const float* __restrict__ A, const float* __restrict__ B,
                    int Md, int Nd, int Kd, int mode,
                    float* __restrict__ dst, int total_len, int row_off)
{
    __shared__ float As[BK][BM];
    __shared__ float Bs[BK][BN];

    int tid = threadIdx.x;
    int tx = tid & 15;          // 0..15 -> col group
    int ty = tid >> 4;          // 0..15 -> row group
    int rowBase = blockIdx.y * BM;
    int colBase = blockIdx.x * BN;

    float acc[8][8];
#pragma unroll
    for (int i = 0; i < 8; i++)
#pragma unroll
        for (int j = 0; j < 8; j++) acc[i][j] = 0.f;

    for (int k0 = 0; k0 < Kd; k0 += BK) {
        // Load 128x16 tiles of A and B, transposed into smem [BK][128]
#pragma unroll
        for (int it = 0; it < 2; it++) {
            int e = tid + it * 256;          // 0..511
            int r = e >> 2;                  // 0..127
            int c4 = (e & 3) * 4;            // 0,4,8,12
            float4 va = *(const float4*)(A + (size_t)(rowBase + r) * Kd + k0 + c4);
            As[c4 + 0][r] = va.x; As[c4 + 1][r] = va.y;
            As[c4 + 2][r] = va.z; As[c4 + 3][r] = va.w;
            float4 vb = *(const float4*)(B + (size_t)(colBase + r) * Kd + k0 + c4);
            Bs[c4 + 0][r] = vb.x; Bs[c4 + 1][r] = vb.y;
            Bs[c4 + 2][r] = vb.z; Bs[c4 + 3][r] = vb.w;
        }
        __syncthreads();

#pragma unroll
        for (int kk = 0; kk < BK; kk++) {
            float a[8], b[8];
            *(float4*)(a)     = *(float4*)&As[kk][ty * 8];
            *(float4*)(a + 4) = *(float4*)&As[kk][ty * 8 + 4];
            *(float4*)(b)     = *(float4*)&Bs[kk][tx * 8];
            *(float4*)(b + 4) = *(float4*)&Bs[kk][tx * 8 + 4];
#pragma unroll
            for (int i = 0; i < 8; i++)
#pragma unroll
                for (int j = 0; j < 8; j++)
                    acc[i][j] += a[i] * b[j];
        }
        __syncthreads();
    }

    if (mode == 0) {
#pragma unroll
        for (int i = 0; i < 8; i++) {
            int m = rowBase + ty * 8 + i;
            float* d = dst + (size_t)m * Nd + colBase + tx * 8;
            *(float4*)(d)     = *(float4*)&acc[i][0];
            *(float4*)(d + 4) = *(float4*)&acc[i][4];
        }
    } else {
#pragma unroll
        for (int i = 0; i < 8; i++) {
            int m = rowBase + ty * 8 + i;
            int bb = m >> 11;            // /SEQ
            int ss = m & (SEQ - 1);
#pragma unroll
            for (int j = 0; j < 8; j++) {
                int n = colBase + tx * 8 + j;
                int hh = n >> 7;         // /DH
                int dd = n & (DH - 1);
                dst[(size_t)(bb * NHEADS + hh) * total_len * DH
                    + (size_t)(row_off + ss) * DH + dd] = acc[i][j];
            }
        }
    }
}

// ---------------------------------------------------------------------------
// Copy past K/V into the concatenated cache output
// ---------------------------------------------------------------------------
__global__ void copy_past_kernel(const float4* __restrict__ pk,
                                 const float4* __restrict__ pv,
                                 float4* __restrict__ Kout,
                                 float4* __restrict__ Vout)
{
    // per head: src PAST*32 float4, dst stride TOTAL*32 float4
    int i = blockIdx.x * blockDim.x + threadIdx.x;      // 0 .. 32*2048*32-1
    const int perHeadSrc = PAST * (DH / 4);             // 65536
    const int perHeadDst = TOTAL * (DH / 4);            // 131072
    int bh  = i / perHeadSrc;
    int rem = i - bh * perHeadSrc;
    Kout[(size_t)bh * perHeadDst + rem] = pk[i];
    Vout[(size_t)bh * perHeadDst + rem] = pv[i];
}

// ---------------------------------------------------------------------------
// Flash attention (fp32, streaming softmax)
// grid: (SEQ/64, B*NHEADS) ; 256 threads
// Q: g_Q (bh, s, dh) ; K,V: concatenated caches in d_out ; O -> g_attn (b*s, d)
// ---------------------------------------------------------------------------
#define BQ 64
#define BKV 64
#define SS_LD 68   // padded leading dim for score tile

__global__ __launch_bounds__(256)
void flash_kernel(const float* __restrict__ Qg, const float* __restrict__ Kg,
                  const float* __restrict__ Vg, float* __restrict__ Og)
{
    extern __shared__ float sm[];
    float* Qs  = sm;                       // [64][128]
    float* Ks  = sm + 8192;                // [64][128]
    float* Vs  = sm + 16384;               // [64][128]
    float* Ss  = sm + 24576;               // [64][SS_LD]
    float* m_s = Ss + 64 * SS_LD;          // [64]
    float* l_s = m_s + 64;                 // [64]
    float* sc_s = l_s + 64;                // [64]

    int tid = threadIdx.x;
    int bh  = blockIdx.y;
    int qb  = blockIdx.x;
    int qbase = qb * BQ;

    const float* Qh = Qg + (size_t)bh * SEQ * DH;
    const float* Kh = Kg + (size_t)bh * TOTAL * DH;
    const float* Vh = Vg + (size_t)bh * TOTAL * DH;

    const float scale = 0.08838834764831845f;   // 1/sqrt(128)

    // Load Q tile (scaled)
#pragma unroll
    for (int it = 0; it < 8; it++) {
        int e = tid + it * 256;      // 0..2047 float4 slots
        int r = e >> 5;              // /32
        int c = (e & 31) * 4;
        float4 v = *(const float4*)(Qh + (size_t)(qbase + r) * DH + c);
        v.x *= scale; v.y *= scale; v.z *= scale; v.w *= scale;
        *(float4*)&Qs[r * DH + c] = v;
    }
    if (tid < 64) { m_s[tid] = -1e30f; l_s[tid] = 0.f; }

    int r0 = (tid >> 4) * 4;     // 4 q-rows per thread
    int c0 = (tid & 15) * 4;     // 4 k-cols per thread (score phase)
    int d0 = (tid & 15) * 8;     // 8 v-dims per thread (PV phase)

    float O[4][8];
#pragma unroll
    for (int i = 0; i < 4; i++)
#pragma unroll
        for (int j = 0; j < 8; j++) O[i][j] = 0.f;

    int nb = (PAST / BKV) + qb + 1;      // kv blocks: full past + causal new part

    for (int kb = 0; kb < nb; kb++) {
        int kstart = kb * BKV;
        __syncthreads();    // previous iteration fully consumed Ks/Vs/Ss

        // Load K and V tiles
#pragma unroll
        for (int it = 0; it < 8; it++) {
            int e = tid + it * 256;
            int r = e >> 5;
            int c = (e & 31) * 4;
            *(float4*)&Ks[r * DH + c] = *(const float4*)(Kh + (size_t)(kstart + r) * DH + c);
            *(float4*)&Vs[r * DH + c] = *(const float4*)(Vh + (size_t)(kstart + r) * DH + c);
        }
        __syncthreads();

        // S = Q K^T  (4x4 per thread)
        float s[4][4];
#pragma unroll
        for (int i = 0; i < 4; i++)
#pragma unroll
            for (int j = 0; j < 4; j++) s[i][j] = 0.f;

#pragma unroll 4
        for (int kk = 0; kk < DH; kk += 4) {
            float4 q4[4], k4[4];
#pragma unroll
            for (int i = 0; i < 4; i++) q4[i] = *(float4*)&Qs[(r0 + i) * DH + kk];
#pragma unroll
            for (int j = 0; j < 4; j++) k4[j] = *(float4*)&Ks[(c0 + j) * DH + kk];
#pragma unroll
            for (int i = 0; i < 4; i++)
#pragma unroll
                for (int j = 0; j < 4; j++) {
                    s[i][j] += q4[i].x * k4[j].x;
                    s[i][j] += q4[i].y * k4[j].y;
                    s[i][j] += q4[i].z * k4[j].z;
                    s[i][j] += q4[i].w * k4[j].w;
                }
        }

        // Causal mask (only the final block of each q-block is partial)
        if (kstart + BKV - 1 > PAST + qbase) {
#pragma unroll
            for (int i = 0; i < 4; i++)
#pragma unroll
                for (int j = 0; j < 4; j++)
                    if (kstart + c0 + j > PAST + qbase + r0 + i) s[i][j] = -1e30f;
        }

#pragma unroll
        for (int i = 0; i < 4; i++)
#pragma unroll
            for (int j = 0; j < 4; j++)
                Ss[(r0 + i) * SS_LD + c0 + j] = s[i][j];
        __syncthreads();

        // Online softmax: 4 threads per row
        {
            int row = tid >> 2;
            int sub = tid & 3;
            float* Sr = &Ss[row * SS_LD + sub * 16];
            float mold = m_s[row];
            float mx = mold;
#pragma unroll
            for (int c = 0; c < 16; c++) mx = fmaxf(mx, Sr[c]);
            mx = fmaxf(mx, __shfl_xor_sync(0xffffffffu, mx, 1));
            mx = fmaxf(mx, __shfl_xor_sync(0xffffffffu, mx, 2));
            float lsum = 0.f;
#pragma unroll
            for (int c = 0; c < 16; c++) {
                float p = __expf(Sr[c] - mx);
                Sr[c] = p;
                lsum += p;
            }
            lsum += __shfl_xor_sync(0xffffffffu, lsum, 1);
            lsum += __shfl_xor_sync(0xffffffffu, lsum, 2);
            if (sub == 0) {
                float sc = __expf(mold - mx);
                sc_s[row] = sc;
                l_s[row] = l_s[row] * sc + lsum;
                m_s[row] = mx;
            }
        }
        __syncthreads();

        // O = O*sc + P @ V
        float scr[4];
#pragma unroll
        for (int i = 0; i < 4; i++) scr[i] = sc_s[r0 + i];
#pragma unroll
        for (int i = 0; i < 4; i++)
#pragma unroll
            for (int j = 0; j < 8; j++) O[i][j] *= scr[i];

#pragma unroll 4
        for (int c = 0; c < BKV; c++) {
            float p[4];
#pragma unroll
            for (int i = 0; i < 4; i++) p[i] = Ss[(r0 + i) * SS_LD + c];
            float4 v0 = *(float4*)&Vs[c * DH + d0];
            float4 v1 = *(float4*)&Vs[c * DH + d0 + 4];
#pragma unroll
            for (int i = 0; i < 4; i++) {
                O[i][0] += p[i] * v0.x;  O[i][1] += p[i] * v0.y;
                O[i][2] += p[i] * v0.z;  O[i][3] += p[i] * v0.w;
                O[i][4] += p[i] * v1.x;  O[i][5] += p[i] * v1.y;
                O[i][6] += p[i] * v1.z;  O[i][7] += p[i] * v1.w;
            }
        }
    }

    // Epilogue: normalize and scatter into (b, s, h*DH+d) layout
    int bb = bh >> 4;
    int hh = bh & 15;
#pragma unroll
    for (int i = 0; i < 4; i++) {
        float inv = 1.0f / l_s[r0 + i];
        float4 o0, o1;
        o0.x = O[i][0] * inv; o0.y = O[i][1] * inv;
        o0.z = O[i][2] * inv; o0.w = O[i][3] * inv;
        o1.x = O[i][4] * inv; o1.y = O[i][5] * inv;
        o1.z = O[i][6] * inv; o1.w = O[i][7] * inv;
        float* dst = Og + (size_t)(bb * SEQ + qbase + r0 + i) * DMODEL + hh * DH + d0;
        *(float4*)(dst)     = o0;
        *(float4*)(dst + 4) = o1;
    }
}

// ---------------------------------------------------------------------------
// Launch
// ---------------------------------------------------------------------------
extern "C" void kernel_launch(void* const* d_in, const int* in_sizes, int n_in,
                              void* d_out, int out_size)
{
    const float* x      = (const float*)d_in[0];
    const float* past_k = (const float*)d_in[1];
    const float* past_v = (const float*)d_in[2];
    const float* Wq     = (const float*)d_in[3];
    const float* Wk     = (const float*)d_in[4];
    const float* Wv     = (const float*)d_in[5];
    const float* Wo     = (const float*)d_in[6];

    float* out  = (float*)d_out;
    float* Kout = out + OUT_ELEMS;
    float* Vout = Kout + KV_ELEMS;

    float* qptr = nullptr;
    float* aptr = nullptr;
    cudaGetSymbolAddress((void**)&qptr, g_Q);
    cudaGetSymbolAddress((void**)&aptr, g_attn);

    dim3 ggrid(DMODEL / BN, MROWS / BM);   // (16, 32)
    dim3 gblk(256);

    // Q/K/V projections (head-split scatter). K/V go straight into the cache output.
    gemm_nt_kernel<<<ggrid, gblk>>>(x, Wq, MROWS, DMODEL, DMODEL, 1, qptr, SEQ, 0);
    gemm_nt_kernel<<<ggrid, gblk>>>(x, Wk, MROWS, DMODEL, DMODEL, 1, Kout, TOTAL, PAST);
    gemm_nt_kernel<<<ggrid, gblk>>>(x, Wv, MROWS, DMODEL, DMODEL, 1, Vout, TOTAL, PAST);

    // Past cache copy
    {
        int n4 = BATCH * NHEADS * PAST * (DH / 4);   // 2,097,152
        copy_past_kernel<<<n4 / 256, 256>>>((const float4*)past_k, (const float4*)past_v,
                                            (float4*)Kout, (float4*)Vout);
    }

    // Flash attention
    {
        size_t smem = (size_t)(24576 + 64 * SS_LD + 3 * 64) * sizeof(float); // 116,480 B
        cudaFuncSetAttribute(flash_kernel, cudaFuncAttributeMaxDynamicSharedMemorySize,
                             (int)smem);
        dim3 fgrid(SEQ / BQ, BATCH * NHEADS);        // (32, 32)
        flash_kernel<<<fgrid, 256, smem>>>(qptr, Kout, Vout, aptr);
    }

    // Output projection
    gemm_nt_kernel<<<ggrid, gblk>>>(aptr, Wo, MROWS, DMODEL, DMODEL, 0, out, 0, 0);

    (void)in_sizes; (void)n_in; (void)out_size;
}

// round 3
// speedup vs baseline: 4.7291x; 4.7291x over previous
#include <cuda_runtime.h>
#include <cuda_bf16.h>
#include <math.h>
#include <stdint.h>

// Problem constants
#define BATCH 2
#define SEQ 2048
#define DMODEL 2048
#define NHEADS 16
#define DH 128
#define PAST 2048
#define TOTAL 4096
#define MROWS (BATCH*SEQ)   // 4096

#define OUT_ELEMS   ((size_t)BATCH*SEQ*DMODEL)
#define KV_ELEMS    ((size_t)BATCH*NHEADS*TOTAL*DH)

// Scratch
__device__ float g_Q[(size_t)BATCH*NHEADS*SEQ*DH];
__device__ float g_attn[(size_t)MROWS*DMODEL];

// ---------------------------------------------------------------------------
// tf32 helpers
// ---------------------------------------------------------------------------
__device__ __forceinline__ uint32_t f2tf32(float x) {
    uint32_t u;
    asm("cvt.rna.tf32.f32 %0, %1;" : "=r"(u) : "f"(x));
    return u;
}

__device__ __forceinline__ void mma_tf32(float* d, const uint32_t* a,
                                         const uint32_t* b, const float* c) {
    asm volatile(
        "mma.sync.aligned.m16n8k8.row.col.f32.tf32.tf32.f32 "
        "{%0,%1,%2,%3}, {%4,%5,%6,%7}, {%8,%9}, {%10,%11,%12,%13};"
        : "=f"(d[0]), "=f"(d[1]), "=f"(d[2]), "=f"(d[3])
        : "r"(a[0]), "r"(a[1]), "r"(a[2]), "r"(a[3]),
          "r"(b[0]), "r"(b[1]),
          "f"(c[0]), "f"(c[1]), "f"(c[2]), "f"(c[3]));
}

// ---------------------------------------------------------------------------
// GEMM (tf32 tensor core): C[m,n] = sum_k A[m,k]*B[n,k]
// A: MxK row-major fp32, B: NxK row-major fp32. K=N=2048 fixed.
// mode 0: dst[m*2048+n]
// mode 1: head-split: dst[(b*16+h)*total*128 + (row_off+s)*128 + d]
// ---------------------------------------------------------------------------
#define GBM 128
#define GBN 128
#define GBK 32
#define GLD 36   // padded smem leading dim (4 mod 32 -> conflict-free frags)

__global__ __launch_bounds__(256)
void gemm_tf32_kernel(const float* __restrict__ A, const float* __restrict__ B,
                      int mode, float* __restrict__ dst, int total_len, int row_off)
{
    __shared__ float As[GBM][GLD];
    __shared__ float Bs[GBN][GLD];

    const int tid = threadIdx.x;
    const int warpid = tid >> 5;
    const int lane = tid & 31;
    const int g = lane >> 2;     // 0..7
    const int t4 = lane & 3;     // 0..3
    const int wr = warpid >> 2;  // 0..1
    const int wc = warpid & 3;   // 0..3
    const int wm0 = wr * 64;
    const int wn0 = wc * 32;

    const int rowBase = blockIdx.y * GBM;
    const int colBase = blockIdx.x * GBN;

    float acc[4][4][4];
#pragma unroll
    for (int i = 0; i < 4; i++)
#pragma unroll
        for (int j = 0; j < 4; j++)
#pragma unroll
            for (int r = 0; r < 4; r++) acc[i][j][r] = 0.f;

    for (int k0 = 0; k0 < DMODEL; k0 += GBK) {
        __syncthreads();
        // Stage A and B tiles (convert to tf32)
#pragma unroll
        for (int it = 0; it < 4; it++) {
            int e = tid + it * 256;
            int r = e >> 3;
            int c4 = (e & 7) * 4;
            float4 va = *(const float4*)(A + (size_t)(rowBase + r) * DMODEL + k0 + c4);
            float4 wa;
            wa.x = __uint_as_float(f2tf32(va.x));
            wa.y = __uint_as_float(f2tf32(va.y));
            wa.z = __uint_as_float(f2tf32(va.z));
            wa.w = __uint_as_float(f2tf32(va.w));
            *(float4*)&As[r][c4] = wa;
            float4 vb = *(const float4*)(B + (size_t)(colBase + r) * DMODEL + k0 + c4);
            float4 wb;
            wb.x = __uint_as_float(f2tf32(vb.x));
            wb.y = __uint_as_float(f2tf32(vb.y));
            wb.z = __uint_as_float(f2tf32(vb.z));
            wb.w = __uint_as_float(f2tf32(vb.w));
            *(float4*)&Bs[r][c4] = wb;
        }
        __syncthreads();

#pragma unroll
        for (int ks = 0; ks < GBK / 8; ks++) {
            int kk = ks * 8;
            uint32_t af[4][4];
#pragma unroll
            for (int i = 0; i < 4; i++) {
                int r = wm0 + i * 16 + g;
                af[i][0] = __float_as_uint(As[r][kk + t4]);
                af[i][1] = __float_as_uint(As[r + 8][kk + t4]);
                af[i][2] = __float_as_uint(As[r][kk + t4 + 4]);
                af[i][3] = __float_as_uint(As[r + 8][kk + t4 + 4]);
            }
            uint32_t bf[4][2];
#pragma unroll
            for (int j = 0; j < 4; j++) {
                int n = wn0 + j * 8 + g;
                bf[j][0] = __float_as_uint(Bs[n][kk + t4]);
                bf[j][1] = __float_as_uint(Bs[n][kk + t4 + 4]);
            }
#pragma unroll
            for (int i = 0; i < 4; i++)
#pragma unroll
                for (int j = 0; j < 4; j++)
                    mma_tf32(acc[i][j], af[i], bf[j], acc[i][j]);
        }
    }

    if (mode == 0) {
#pragma unroll
        for (int i = 0; i < 4; i++)
#pragma unroll
            for (int j = 0; j < 4; j++) {
                int m = rowBase + wm0 + i * 16 + g;
                int n = colBase + wn0 + j * 8 + 2 * t4;
                *(float2*)(dst + (size_t)m * DMODEL + n) =
                    make_float2(acc[i][j][0], acc[i][j][1]);
                *(float2*)(dst + (size_t)(m + 8) * DMODEL + n) =
                    make_float2(acc[i][j][2], acc[i][j][3]);
            }
    } else {
#pragma unroll
        for (int i = 0; i < 4; i++)
#pragma unroll
            for (int j = 0; j < 4; j++) {
                int n = colBase + wn0 + j * 8 + 2 * t4;
                int hh = n >> 7;
                int dd = n & (DH - 1);
#pragma unroll
                for (int half = 0; half < 2; half++) {
                    int m = rowBase + wm0 + i * 16 + g + half * 8;
                    int bb = m >> 11;
                    int ss = m & (SEQ - 1);
                    float* p = dst + (size_t)(bb * NHEADS + hh) * total_len * DH
                                   + (size_t)(row_off + ss) * DH + dd;
                    *(float2*)p = make_float2(acc[i][j][half * 2], acc[i][j][half * 2 + 1]);
                }
            }
    }
}

// ---------------------------------------------------------------------------
// Copy past K/V into concatenated caches
// ---------------------------------------------------------------------------
__global__ void copy_past_kernel(const float4* __restrict__ pk,
                                 const float4* __restrict__ pv,
                                 float4* __restrict__ Kout,
                                 float4* __restrict__ Vout)
{
    int i = blockIdx.x * blockDim.x + threadIdx.x;
    const int perHeadSrc = PAST * (DH / 4);
    const int perHeadDst = TOTAL * (DH / 4);
    int bh  = i / perHeadSrc;
    int rem = i - bh * perHeadSrc;
    Kout[(size_t)bh * perHeadDst + rem] = pk[i];
    Vout[(size_t)bh * perHeadDst + rem] = pv[i];
}

// ---------------------------------------------------------------------------
// Flash attention with tf32 mma. BQ=64, BKV=64, 256 threads.
// ---------------------------------------------------------------------------
#define BQ 64
#define BKV 64
#define QLD 132   // 128 + 4 (4 mod 32 -> conflict-free)
#define SLD 68    // 64 + 4

// smem float offsets
#define QS_OFF 0
#define KS_OFF (64*QLD)                 // 8448
#define VS_OFF (2*64*QLD)               // 16896
#define SS_OFF (3*64*QLD)               // 25344
#define M_OFF  (SS_OFF + 64*SLD)        // 29696
#define L_OFF  (M_OFF + 64)
#define SC_OFF (L_OFF + 64)
#define FLASH_SMEM_FLOATS (SC_OFF + 64) // 29888

__global__ __launch_bounds__(256)
void flash_tf32_kernel(const float* __restrict__ Qg, const float* __restrict__ Kg,
                       const float* __restrict__ Vg, float* __restrict__ Og)
{
    extern __shared__ float sm[];
    float* Qs = sm + QS_OFF;
    float* Ks = sm + KS_OFF;
    float* Vs = sm + VS_OFF;
    float* Ss = sm + SS_OFF;
    float* m_s = sm + M_OFF;
    float* l_s = sm + L_OFF;
    float* sc_s = sm + SC_OFF;

    const int tid = threadIdx.x;
    const int warpid = tid >> 5;
    const int lane = tid & 31;
    const int g = lane >> 2;
    const int t4 = lane & 3;

    // S phase warp layout: rows (warpid&3)*16, cols (warpid>>2)*32
    const int wmS = (warpid & 3) * 16;
    const int wnS = (warpid >> 2) * 32;
    // PV phase warp layout: rows (warpid>>2)*32, cols (warpid&3)*32
    const int wmP = (warpid >> 2) * 32;
    const int wnP = (warpid & 3) * 32;

    const int bh = blockIdx.y;
    const int qb = blockIdx.x;
    const int qbase = qb * BQ;

    const float* Qh = Qg + (size_t)bh * SEQ * DH;
    const float* Kh = Kg + (size_t)bh * TOTAL * DH;
    const float* Vh = Vg + (size_t)bh * TOTAL * DH;

    const float scale = 0.08838834764831845f;   // 1/sqrt(128)

    // Load Q tile (scaled, tf32)
#pragma unroll
    for (int it = 0; it < 8; it++) {
        int e = tid + it * 256;
        int r = e >> 5;
        int c = (e & 31) * 4;
        float4 v = *(const float4*)(Qh + (size_t)(qbase + r) * DH + c);
        float4 w;
        w.x = __uint_as_float(f2tf32(v.x * scale));
        w.y = __uint_as_float(f2tf32(v.y * scale));
        w.z = __uint_as_float(f2tf32(v.z * scale));
        w.w = __uint_as_float(f2tf32(v.w * scale));
        *(float4*)&Qs[r * QLD + c] = w;
    }
    if (tid < 64) { m_s[tid] = -1e30f; l_s[tid] = 0.f; }

    float oacc[2][4][4];
#pragma unroll
    for (int i = 0; i < 2; i++)
#pragma unroll
        for (int j = 0; j < 4; j++)
#pragma unroll
            for (int r = 0; r < 4; r++) oacc[i][j][r] = 0.f;

    const int nb = (PAST / BKV) + qb + 1;

    for (int kb = 0; kb < nb; kb++) {
        const int kstart = kb * BKV;
        __syncthreads();   // previous iteration fully consumed Ks/Vs/Ss

        // Load K, V tiles (tf32)
#pragma unroll
        for (int it = 0; it < 8; it++) {
            int e = tid + it * 256;
            int r = e >> 5;
            int c = (e & 31) * 4;
            float4 vk = *(const float4*)(Kh + (size_t)(kstart + r) * DH + c);
            float4 wk;
            wk.x = __uint_as_float(f2tf32(vk.x));
            wk.y = __uint_as_float(f2tf32(vk.y));
            wk.z = __uint_as_float(f2tf32(vk.z));
            wk.w = __uint_as_float(f2tf32(vk.w));
            *(float4*)&Ks[r * QLD + c] = wk;
            float4 vv = *(const float4*)(Vh + (size_t)(kstart + r) * DH + c);
            float4 wv;
            wv.x = __uint_as_float(f2tf32(vv.x));
            wv.y = __uint_as_float(f2tf32(vv.y));
            wv.z = __uint_as_float(f2tf32(vv.z));
            wv.w = __uint_as_float(f2tf32(vv.w));
            *(float4*)&Vs[r * QLD + c] = wv;
        }
        __syncthreads();

        // S = Q K^T : each warp 16x32 tile
        float sacc[4][4];
#pragma unroll
        for (int j = 0; j < 4; j++)
#pragma unroll
            for (int r = 0; r < 4; r++) sacc[j][r] = 0.f;

#pragma unroll
        for (int ks = 0; ks < DH / 8; ks++) {
            int kk = ks * 8;
            uint32_t af[4];
            af[0] = __float_as_uint(Qs[(wmS + g) * QLD + kk + t4]);
            af[1] = __float_as_uint(Qs[(wmS + g + 8) * QLD + kk + t4]);
            af[2] = __float_as_uint(Qs[(wmS + g) * QLD + kk + t4 + 4]);
            af[3] = __float_as_uint(Qs[(wmS + g + 8) * QLD + kk + t4 + 4]);
#pragma unroll
            for (int j = 0; j < 4; j++) {
                uint32_t bf[2];
                int n = wnS + j * 8 + g;
                bf[0] = __float_as_uint(Ks[n * QLD + kk + t4]);
                bf[1] = __float_as_uint(Ks[n * QLD + kk + t4 + 4]);
                mma_tf32(sacc[j], af, bf, sacc[j]);
            }
        }
#pragma unroll
        for (int j = 0; j < 4; j++) {
            int n = wnS + j * 8 + 2 * t4;
            *(float2*)&Ss[(wmS + g) * SLD + n] = make_float2(sacc[j][0], sacc[j][1]);
            *(float2*)&Ss[(wmS + g + 8) * SLD + n] = make_float2(sacc[j][2], sacc[j][3]);
        }
        __syncthreads();

        // Online softmax (4 threads per row, 16 cols each), causal masking here
        {
            int row = tid >> 2;
            int sub = tid & 3;
            float* Sr = &Ss[row * SLD + sub * 16];
            int allowed = PAST + qbase + row - kstart;  // max valid col (inclusive)
            float mold = m_s[row];
            float mx = mold;
            float vbuf[16];
#pragma unroll
            for (int c = 0; c < 16; c++) {
                int cg = sub * 16 + c;
                float v = (cg <= allowed) ? Sr[c] : -1e30f;
                vbuf[c] = v;
                mx = fmaxf(mx, v);
            }
            mx = fmaxf(mx, __shfl_xor_sync(0xffffffffu, mx, 1));
            mx = fmaxf(mx, __shfl_xor_sync(0xffffffffu, mx, 2));
            float lsum = 0.f;
#pragma unroll
            for (int c = 0; c < 16; c++) {
                float p = __expf(vbuf[c] - mx);
                lsum += p;
                Sr[c] = __uint_as_float(f2tf32(p));
            }
            lsum += __shfl_xor_sync(0xffffffffu, lsum, 1);
            lsum += __shfl_xor_sync(0xffffffffu, lsum, 2);
            if (sub == 0) {
                float sc = __expf(mold - mx);
                sc_s[row] = sc;
                l_s[row] = l_s[row] * sc + lsum;
                m_s[row] = mx;
            }
        }
        __syncthreads();

        // O = O*sc + P @ V : each warp 32x32 tile of O
#pragma unroll
        for (int i = 0; i < 2; i++) {
            int rlo = wmP + i * 16 + g;
            float sl = sc_s[rlo];
            float sh = sc_s[rlo + 8];
#pragma unroll
            for (int j = 0; j < 4; j++) {
                oacc[i][j][0] *= sl; oacc[i][j][1] *= sl;
                oacc[i][j][2] *= sh; oacc[i][j][3] *= sh;
            }
        }
#pragma unroll
        for (int ks = 0; ks < BKV / 8; ks++) {
            int kk = ks * 8;
            uint32_t af[2][4];
#pragma unroll
            for (int i = 0; i < 2; i++) {
                int r = wmP + i * 16 + g;
                af[i][0] = __float_as_uint(Ss[r * SLD + kk + t4]);
                af[i][1] = __float_as_uint(Ss[(r + 8) * SLD + kk + t4]);
                af[i][2] = __float_as_uint(Ss[r * SLD + kk + t4 + 4]);
                af[i][3] = __float_as_uint(Ss[(r + 8) * SLD + kk + t4 + 4]);
            }
#pragma unroll
            for (int j = 0; j < 4; j++) {
                uint32_t bf[2];
                int n = wnP + j * 8 + g;   // output dim index
                bf[0] = __float_as_uint(Vs[(kk + t4) * QLD + n]);
                bf[1] = __float_as_uint(Vs[(kk + t4 + 4) * QLD + n]);
#pragma unroll
                for (int i = 0; i < 2; i++)
                    mma_tf32(oacc[i][j], af[i], bf, oacc[i][j]);
            }
        }
    }

    __syncthreads();
    // Epilogue: normalize, scatter to (b, s, h*DH+d)
    const int bb = bh >> 4;
    const int hh = bh & 15;
#pragma unroll
    for (int i = 0; i < 2; i++) {
#pragma unroll
        for (int half = 0; half < 2; half++) {
            int r = wmP + i * 16 + g + half * 8;
            float inv = 1.0f / l_s[r];
            float* dst = Og + (size_t)(bb * SEQ + qbase + r) * DMODEL + hh * DH;
#pragma unroll
            for (int j = 0; j < 4; j++) {
                int n = wnP + j * 8 + 2 * t4;
                *(float2*)(dst + n) = make_float2(oacc[i][j][half * 2] * inv,
                                                  oacc[i][j][half * 2 + 1] * inv);
            }
        }
    }
}

// ---------------------------------------------------------------------------
// Launch
// ---------------------------------------------------------------------------
extern "C" void kernel_launch(void* const* d_in, const int* in_sizes, int n_in,
                              void* d_out, int out_size)
{
    const float* x      = (const float*)d_in[0];
    const float* past_k = (const float*)d_in[1];
    const float* past_v = (const float*)d_in[2];
    const float* Wq     = (const float*)d_in[3];
    const float* Wk     = (const float*)d_in[4];
    const float* Wv     = (const float*)d_in[5];
    const float* Wo     = (const float*)d_in[6];

    float* out  = (float*)d_out;
    float* Kout = out + OUT_ELEMS;
    float* Vout = Kout + KV_ELEMS;

    float* qptr = nullptr;
    float* aptr = nullptr;
    cudaGetSymbolAddress((void**)&qptr, g_Q);
    cudaGetSymbolAddress((void**)&aptr, g_attn);

    dim3 ggrid(DMODEL / GBN, MROWS / GBM);   // (16, 32)
    dim3 gblk(256);

    gemm_tf32_kernel<<<ggrid, gblk>>>(x, Wq, 1, qptr, SEQ, 0);
    gemm_tf32_kernel<<<ggrid, gblk>>>(x, Wk, 1, Kout, TOTAL, PAST);
    gemm_tf32_kernel<<<ggrid, gblk>>>(x, Wv, 1, Vout, TOTAL, PAST);

    {
        int n4 = BATCH * NHEADS * PAST * (DH / 4);
        copy_past_kernel<<<n4 / 256, 256>>>((const float4*)past_k, (const float4*)past_v,
                                            (float4*)Kout, (float4*)Vout);
    }

    {
        size_t smem = (size_t)FLASH_SMEM_FLOATS * sizeof(float);   // 119,552 B
        cudaFuncSetAttribute(flash_tf32_kernel,
                             cudaFuncAttributeMaxDynamicSharedMemorySize, (int)smem);
        dim3 fgrid(SEQ / BQ, BATCH * NHEADS);
        flash_tf32_kernel<<<fgrid, 256, smem>>>(qptr, Kout, Vout, aptr);
    }

    gemm_tf32_kernel<<<ggrid, gblk>>>(aptr, Wo, 0, out, 0, 0);

    (void)in_sizes; (void)n_in; (void)out_size;
}